// round 3
// baseline (speedup 1.0000x reference)
#include <cuda_runtime.h>
#include <cuda_bf16.h>

// Output layout (flattened f32 concat of the reference tuple):
//   [0, 3V)                      verts_3d   (V x 3)
//   [3V, 3V + Fe)                faces cast to f32 (Fe = in_sizes[3])
//   [3V + Fe, 3V + Fe + V*D)     verts_features copy
//
// One fused kernel, three sequential region loops. Features copy is the
// dominant region (256 MB r + 256 MB w): unrolled x4 grid-stride with all
// four LDG.128 issued before the STGs (MLP batching), streaming cache hints.

__global__ void __launch_bounds__(256) fused_all_kernel(
    const float* __restrict__ verts_logit,
    const float* __restrict__ verts_features,
    const float* __restrict__ boundary,
    const int*   __restrict__ faces,
    float* __restrict__ out,
    int V, int faces_elems, int feat_elems,
    int feat_out_aligned)   // 1 if (3V + faces_elems) % 4 == 0
{
    const long long threeV = 3LL * V;
    float* __restrict__ out_faces    = out + threeV;
    float* __restrict__ out_features = out_faces + faces_elems;

    const long long Wfeat  = feat_elems >> 2;       // feat_elems %4 == 0
    const long long Wfaces = (faces_elems + 3) >> 2;

    const long long S   = (long long)gridDim.x * blockDim.x;
    const long long tid = (long long)blockIdx.x * blockDim.x + threadIdx.x;

    // ---- region 1: bulk features copy (dominant) ----
    const float4* __restrict__ src = (const float4*)verts_features;
    if (feat_out_aligned) {
        float4* __restrict__ dst = (float4*)out_features;
        long long i = tid;
        for (; i + 3LL * S < Wfeat; i += 4LL * S) {
            float4 a = __ldcs(src + i);
            float4 b = __ldcs(src + i + S);
            float4 c = __ldcs(src + i + 2LL * S);
            float4 d = __ldcs(src + i + 3LL * S);
            __stcs(dst + i,           a);
            __stcs(dst + i + S,       b);
            __stcs(dst + i + 2LL * S, c);
            __stcs(dst + i + 3LL * S, d);
        }
        for (; i < Wfeat; i += S)
            __stcs(dst + i, __ldcs(src + i));
    } else {
        long long i = tid;
        for (; i + 3LL * S < Wfeat; i += 4LL * S) {
            float4 a = __ldcs(src + i);
            float4 b = __ldcs(src + i + S);
            float4 c = __ldcs(src + i + 2LL * S);
            float4 d = __ldcs(src + i + 3LL * S);
            float* p0 = out_features + (i << 2);
            float* p1 = out_features + ((i + S) << 2);
            float* p2 = out_features + ((i + 2LL * S) << 2);
            float* p3 = out_features + ((i + 3LL * S) << 2);
            __stcs(p0, a.x); __stcs(p0+1, a.y); __stcs(p0+2, a.z); __stcs(p0+3, a.w);
            __stcs(p1, b.x); __stcs(p1+1, b.y); __stcs(p1+2, b.z); __stcs(p1+3, b.w);
            __stcs(p2, c.x); __stcs(p2+1, c.y); __stcs(p2+2, c.z); __stcs(p2+3, c.w);
            __stcs(p3, d.x); __stcs(p3+1, d.y); __stcs(p3+2, d.z); __stcs(p3+3, d.w);
        }
        for (; i < Wfeat; i += S) {
            float4 a = __ldcs(src + i);
            float* p = out_features + (i << 2);
            __stcs(p, a.x); __stcs(p+1, a.y); __stcs(p+2, a.z); __stcs(p+3, a.w);
        }
    }

    // ---- region 2: faces int32 -> float32 ----
    for (long long j = tid; j < Wfaces; j += S) {
        const long long e = j << 2;
        if (e + 4 <= faces_elems) {
            const int4 f = __ldcs((const int4*)faces + j);
            float4 o;
            o.x = (float)f.x; o.y = (float)f.y;
            o.z = (float)f.z; o.w = (float)f.w;
            __stcs((float4*)out_faces + j, o);   // offset 3V %4 == 0
        } else {
            for (long long k = e; k < faces_elems; k++)
                out_faces[k] = (float)__ldg(faces + k);
        }
    }

    // ---- region 3: verts_3d = sigmoid(logit)*2-1 (rows 0..3 = boundary) ----
    for (long long i = tid; i < V; i += S) {
        float x, y;
        if (i < 4) {
            x = boundary[2 * i];
            y = boundary[2 * i + 1];
        } else {
            const float2 l = __ldg((const float2*)verts_logit + i);
            x = 2.0f / (1.0f + __expf(-l.x)) - 1.0f;
            y = 2.0f / (1.0f + __expf(-l.y)) - 1.0f;
        }
        float* d = out + 3LL * i;
        d[0] = x; d[1] = y; d[2] = 1.0f;
    }
}

extern "C" void kernel_launch(void* const* d_in, const int* in_sizes, int n_in,
                              void* d_out, int out_size) {
    const float* verts_logit    = (const float*)d_in[0];   // V*2
    const float* verts_features = (const float*)d_in[1];   // V*D
    const float* boundary       = (const float*)d_in[2];   // 4*2
    const int*   faces          = (const int*)d_in[3];     // F*3 (int32)

    const int V           = in_sizes[0] / 2;
    const int feat_elems  = in_sizes[1];
    const int faces_elems = in_sizes[3];

    const int feat_out_aligned = (((3LL * V + faces_elems) & 3) == 0) ? 1 : 0;

    const int threads = 256;
    // Exactly one resident wave: 8 blocks/SM x 148 SMs (2048 thr/SM cap).
    int blocks = 148 * 8;
    const long long total = (long long)(feat_elems >> 2)
                          + ((faces_elems + 3) >> 2) + V;
    const long long need = (total + threads - 1) / threads;
    if (need < blocks) blocks = (int)need;
    if (blocks < 1) blocks = 1;

    fused_all_kernel<<<blocks, threads>>>(
        verts_logit, verts_features, boundary, faces, (float*)d_out,
        V, faces_elems, feat_elems, feat_out_aligned);
}

// round 4
// speedup vs baseline: 1.1618x; 1.1618x over previous
#include <cuda_runtime.h>
#include <cuda_bf16.h>

// Output layout (flattened f32 concat of the reference tuple):
//   [0, 3V)                      verts_3d   (V x 3)
//   [3V, 3V + Fe)                faces cast to f32 (Fe = in_sizes[3])
//   [3V + Fe, 3V + Fe + V*D)     verts_features copy
//
// One fused kernel over a flat work-item space (R1 structure, occ-first):
//   - __launch_bounds__(256, 8) caps regs at 32 -> 8 blocks/SM resident
//   - features loop: x2 interleaved unroll (2 LDG.128 in flight per thread)
//   - streaming cache hints (touch-once data)

__global__ void __launch_bounds__(256, 8) fused_all_kernel(
    const float* __restrict__ verts_logit,
    const float* __restrict__ verts_features,
    const float* __restrict__ boundary,
    const int*   __restrict__ faces,
    float* __restrict__ out,
    int V, int faces_elems, int feat_elems,
    int feat_out_aligned)   // 1 if (3V + faces_elems) % 4 == 0
{
    const long long threeV = 3LL * V;
    float* __restrict__ out_faces    = out + threeV;
    float* __restrict__ out_features = out_faces + faces_elems;

    const long long Wfeat  = feat_elems >> 2;       // feat_elems %4 == 0
    const long long Wfaces = (faces_elems + 3) >> 2;

    const long long S   = (long long)gridDim.x * blockDim.x;
    const long long tid = (long long)blockIdx.x * blockDim.x + threadIdx.x;

    // ---- region 1: bulk features copy (dominant, 256MB r + 256MB w) ----
    const float4* __restrict__ src = (const float4*)verts_features;
    if (feat_out_aligned) {
        float4* __restrict__ dst = (float4*)out_features;
        long long i = tid;
        const long long limit = Wfeat - S;          // valid when i + S < Wfeat
        for (; i < limit; i += 2LL * S) {
            float4 a = __ldcs(src + i);
            float4 b = __ldcs(src + i + S);
            __stcs(dst + i,     a);
            __stcs(dst + i + S, b);
        }
        for (; i < Wfeat; i += S)
            __stcs(dst + i, __ldcs(src + i));
    } else {
        // dst not 16B-aligned: aligned LDG.128 + 4 scalar streaming stores.
        for (long long i = tid; i < Wfeat; i += S) {
            float4 a = __ldcs(src + i);
            float* p = out_features + (i << 2);
            __stcs(p, a.x); __stcs(p + 1, a.y);
            __stcs(p + 2, a.z); __stcs(p + 3, a.w);
        }
    }

    // ---- region 2: faces int32 -> float32, 4 elems/item ----
    for (long long j = tid; j < Wfaces; j += S) {
        const long long e = j << 2;
        if (e + 4 <= faces_elems) {
            const int4 f = __ldcs((const int4*)faces + j);
            float4 o;
            o.x = (float)f.x; o.y = (float)f.y;
            o.z = (float)f.z; o.w = (float)f.w;
            __stcs((float4*)out_faces + j, o);      // offset 3V %4 == 0
        } else {
            for (long long k = e; k < faces_elems; k++)
                out_faces[k] = (float)__ldg(faces + k);
        }
    }

    // ---- region 3: verts_3d = sigmoid(logit)*2-1 (rows 0..3 = boundary) ----
    for (long long i = tid; i < V; i += S) {
        float x, y;
        if (i < 4) {
            x = boundary[2 * i];
            y = boundary[2 * i + 1];
        } else {
            const float2 l = __ldg((const float2*)verts_logit + i);
            x = 2.0f / (1.0f + __expf(-l.x)) - 1.0f;
            y = 2.0f / (1.0f + __expf(-l.y)) - 1.0f;
        }
        float* d = out + 3LL * i;
        d[0] = x; d[1] = y; d[2] = 1.0f;
    }
}

extern "C" void kernel_launch(void* const* d_in, const int* in_sizes, int n_in,
                              void* d_out, int out_size) {
    const float* verts_logit    = (const float*)d_in[0];   // V*2
    const float* verts_features = (const float*)d_in[1];   // V*D
    const float* boundary       = (const float*)d_in[2];   // 4*2
    const int*   faces          = (const int*)d_in[3];     // F*3 (int32)

    const int V           = in_sizes[0] / 2;
    const int feat_elems  = in_sizes[1];
    const int faces_elems = in_sizes[3];

    const int feat_out_aligned = (((3LL * V + faces_elems) & 3) == 0) ? 1 : 0;

    const int threads = 256;
    int blocks = 148 * 16;                     // same coverage as the 87.9us run
    const long long total = (long long)(feat_elems >> 2)
                          + ((faces_elems + 3) >> 2) + V;
    const long long need = (total + threads - 1) / threads;
    if (need < blocks) blocks = (int)need;
    if (blocks < 1) blocks = 1;

    fused_all_kernel<<<blocks, threads>>>(
        verts_logit, verts_features, boundary, faces, (float*)d_out,
        V, faces_elems, feat_elems, feat_out_aligned);
}

// round 5
// speedup vs baseline: 1.1943x; 1.0280x over previous
#include <cuda_runtime.h>
#include <cuda_bf16.h>

// Output layout (flattened f32 concat of the reference tuple):
//   [0, 3V)                      verts_3d   (V x 3)
//   [3V, 3V + Fe)                faces cast to f32 (Fe = in_sizes[3])
//   [3V + Fe, 3V + Fe + V*D)     verts_features copy
//
// R1 scaffold (flat work-item space + region branch, one wave-dense grid),
// features region upgraded to 256-bit ld/st (Blackwell LDG.256/STG.256)
// when the dst slice is 32B-aligned. feat_mode: 2 = v8 (mod 8), 1 = v4
// (mod 4), 0 = v4 load + scalar stores.

__global__ void __launch_bounds__(256, 8) fused_all_kernel(
    const float* __restrict__ verts_logit,
    const float* __restrict__ verts_features,
    const float* __restrict__ boundary,
    const int*   __restrict__ faces,
    float* __restrict__ out,
    int V, int faces_elems, int feat_elems,
    int feat_mode)
{
    const long long threeV = 3LL * V;
    float* __restrict__ out_faces    = out + threeV;
    float* __restrict__ out_features = out_faces + faces_elems;

    // feat work granularity: 8 floats in v8 mode, else 4
    const long long Wfeat  = (feat_mode == 2) ? (feat_elems >> 3)
                                              : (feat_elems >> 2);
    const long long Wfaces = (faces_elems + 3) >> 2;
    const long long total  = Wfeat + Wfaces + V;

    const long long S = (long long)gridDim.x * blockDim.x;
    for (long long idx = (long long)blockIdx.x * blockDim.x + threadIdx.x;
         idx < total; idx += S) {
        if (idx < Wfeat) {
            if (feat_mode == 2) {
                // ---- 256-bit path: 1 LDG.256 + 1 STG.256 per item ----
                const float* s = verts_features + (idx << 3);
                float*       d = out_features   + (idx << 3);
                float a0, a1, a2, a3, a4, a5, a6, a7;
                asm volatile(
                    "ld.global.nc.v8.f32 {%0,%1,%2,%3,%4,%5,%6,%7}, [%8];"
                    : "=f"(a0), "=f"(a1), "=f"(a2), "=f"(a3),
                      "=f"(a4), "=f"(a5), "=f"(a6), "=f"(a7)
                    : "l"(s));
                asm volatile(
                    "st.global.v8.f32 [%0], {%1,%2,%3,%4,%5,%6,%7,%8};"
                    :: "l"(d),
                       "f"(a0), "f"(a1), "f"(a2), "f"(a3),
                       "f"(a4), "f"(a5), "f"(a6), "f"(a7)
                    : "memory");
            } else if (feat_mode == 1) {
                const float4 v = __ldg((const float4*)verts_features + idx);
                ((float4*)out_features)[idx] = v;
            } else {
                const float4 v = __ldg((const float4*)verts_features + idx);
                float* d = out_features + (idx << 2);
                d[0] = v.x; d[1] = v.y; d[2] = v.z; d[3] = v.w;
            }
        } else if (idx < Wfeat + Wfaces) {
            // ---- faces int32 -> float32, 4 elems/item ----
            const long long j = idx - Wfeat;
            const long long e = j << 2;
            if (e + 4 <= faces_elems) {
                const int4 f = __ldg((const int4*)faces + j);
                float4 o;
                o.x = (float)f.x; o.y = (float)f.y;
                o.z = (float)f.z; o.w = (float)f.w;
                ((float4*)out_faces)[j] = o;       // offset 3V %4 == 0
            } else {
                for (long long k = e; k < faces_elems; k++)
                    out_faces[k] = (float)__ldg(faces + k);
            }
        } else {
            // ---- verts_3d: sigmoid(logit)*2-1 (rows 0..3 = boundary) ----
            const long long i = idx - Wfeat - Wfaces;
            float x, y;
            if (i < 4) {
                x = boundary[2 * i];
                y = boundary[2 * i + 1];
            } else {
                const float2 l = __ldg((const float2*)verts_logit + i);
                x = 2.0f / (1.0f + __expf(-l.x)) - 1.0f;
                y = 2.0f / (1.0f + __expf(-l.y)) - 1.0f;
            }
            float* d = out + 3LL * i;
            d[0] = x; d[1] = y; d[2] = 1.0f;
        }
    }
}

extern "C" void kernel_launch(void* const* d_in, const int* in_sizes, int n_in,
                              void* d_out, int out_size) {
    const float* verts_logit    = (const float*)d_in[0];   // V*2
    const float* verts_features = (const float*)d_in[1];   // V*D
    const float* boundary       = (const float*)d_in[2];   // 4*2
    const int*   faces          = (const int*)d_in[3];     // F*3 (int32)

    const int V           = in_sizes[0] / 2;
    const int feat_elems  = in_sizes[1];                   // V*128, %8 == 0
    const int faces_elems = in_sizes[3];

    const long long off = 3LL * V + faces_elems;           // dst slice offset
    int feat_mode;
    if ((off & 7) == 0)      feat_mode = 2;                // 32B aligned: v8
    else if ((off & 3) == 0) feat_mode = 1;                // 16B aligned: v4
    else                     feat_mode = 0;                // scalar stores

    const int threads = 256;
    int blocks = 148 * 16;
    const long long Wfeat = (feat_mode == 2) ? (feat_elems >> 3)
                                             : (feat_elems >> 2);
    const long long total = Wfeat + ((faces_elems + 3) >> 2) + V;
    const long long need = (total + threads - 1) / threads;
    if (need < blocks) blocks = (int)need;
    if (blocks < 1) blocks = 1;

    fused_all_kernel<<<blocks, threads>>>(
        verts_logit, verts_features, boundary, faces, (float*)d_out,
        V, faces_elems, feat_elems, feat_mode);
}